// round 3
// baseline (speedup 1.0000x reference)
#include <cuda_runtime.h>
#include <cstdint>

#define RES   64
#define CH    8
#define NB    64
#define CORE  32
#define POS   16
#define DIMSZ (CORE*CORE*CORE*CH)   // 262144
#define BATCH 32

#define BGROUPS 4                   // batch split: 4 groups of 8
#define BPG     (BATCH / BGROUPS)   // 8 batches per thread
#define DIMS_PER_TH 4               // float4 U loads
#define COMPUTE_BLOCKS (DIMSZ / (256 * DIMS_PER_TH) * BGROUPS)  // 256*4 = 1024

#define F4_TOTAL  (BATCH*CH*RES*RES*RES/4)   // 16,777,216 float4
#define F4_PER_TH 8
#define ZERO_BLOCKS (F4_TOTAL / (256 * F4_PER_TH))  // 8192
#define GRID (COMPUTE_BLOCKS + ZERO_BLOCKS)

// Fused kernel:
//  blocks [0, 1024):      (L*z)@U + mu for one batch-group of 8, scattered into core
//  blocks [1024, 9216):   zero-fill the periphery (skip core region)
__global__ void __launch_bounds__(256, 4) core_subspace_fused(
    const float* __restrict__ z,   // (32, 64)
    const float* __restrict__ U,   // (64, 262144)
    const float* __restrict__ L,   // (64,)
    const float* __restrict__ mu,  // (262144,)
    float* __restrict__ out)       // (32, 8, 64, 64, 64)
{
    const int tid = threadIdx.x;

    if (blockIdx.x >= COMPUTE_BLOCKS) {
        // ---------------- periphery zero-fill ----------------
        const int zb = blockIdx.x - COMPUTE_BLOCKS;
        const float4 zero4 = make_float4(0.f, 0.f, 0.f, 0.f);
        float4* o4 = reinterpret_cast<float4*>(out);
#pragma unroll
        for (int c = 0; c < F4_PER_TH; c++) {
            const int f = zb * (256 * F4_PER_TH) + c * 256 + tid;
            // f = ((((b*8+ch)*64 + i)*64) + j)*16 + w4
            const unsigned w4 = f & 15;
            const unsigned j  = (f >> 4)  & 63;
            const unsigned i  = (f >> 10) & 63;
            const bool in_core = (i - 16u < 32u) & (j - 16u < 32u) & (w4 - 4u < 8u);
            if (!in_core) o4[f] = zero4;   // core is written by compute blocks
        }
        return;
    }

    // ---------------- GEMM + scatter ----------------
    // zL packed as duplicated f32x2 pairs; one LDS.128 per (batch, k-pair).
    __shared__ alignas(16) unsigned long long s_zl[BATCH * NB];  // 16 KB

    for (int idx = tid; idx < BATCH * NB; idx += 256) {
        float v = L[idx & (NB - 1)] * z[idx];
        unsigned int vb = __float_as_uint(v);
        unsigned long long p;
        asm("mov.b64 %0, {%1, %1};" : "=l"(p) : "r"(vb));
        s_zl[idx] = p;
    }
    __syncthreads();

    // Group-minor block order: same dim-chunk, different batch groups are
    // adjacent -> concurrent -> U re-reads hit L2.
    const int bg       = blockIdx.x & (BGROUPS - 1);   // batch group 0..3
    const int dimchunk = blockIdx.x >> 2;              // 0..255
    const int b0       = bg * BPG;                     // first batch of group

    const int d0 = (dimchunk * 256 + tid) * DIMS_PER_TH;  // dim index, mult of 4

    const ulonglong2 mu4 =
        *reinterpret_cast<const ulonglong2*>(mu + d0);

    unsigned long long accL[BPG], accH[BPG];
#pragma unroll
    for (int b = 0; b < BPG; b++) { accL[b] = mu4.x; accH[b] = mu4.y; }

    const float* Up = U + d0;
    const ulonglong2* zl2 = reinterpret_cast<const ulonglong2*>(s_zl);

#pragma unroll 2
    for (int kp = 0; kp < NB / 2; kp++) {
        const ulonglong2 ua =
            *reinterpret_cast<const ulonglong2*>(Up + (size_t)(2 * kp)     * DIMSZ);
        const ulonglong2 ub =
            *reinterpret_cast<const ulonglong2*>(Up + (size_t)(2 * kp + 1) * DIMSZ);
#pragma unroll
        for (int b = 0; b < BPG; b++) {
            const ulonglong2 zz = zl2[(b0 + b) * (NB / 2) + kp];  // LDS.128 bcast
            asm("fma.rn.f32x2 %0, %1, %2, %0;" : "+l"(accL[b]) : "l"(ua.x), "l"(zz.x));
            asm("fma.rn.f32x2 %0, %1, %2, %0;" : "+l"(accH[b]) : "l"(ua.y), "l"(zz.x));
            asm("fma.rn.f32x2 %0, %1, %2, %0;" : "+l"(accL[b]) : "l"(ub.x), "l"(zz.y));
            asm("fma.rn.f32x2 %0, %1, %2, %0;" : "+l"(accH[b]) : "l"(ub.y), "l"(zz.y));
        }
    }

    // Scatter the 4-dim chunk into the core region.
    // dim = ((c*32 + i)*32 + j)*32 + w, w = d0 & 31 (multiple of 4 -> 16B aligned)
    const int w = d0 & 31;
    const int j = (d0 >> 5) & 31;
    const int i = (d0 >> 10) & 31;
    const int c = d0 >> 15;

    const size_t obase = (size_t)c * (RES * RES * RES)
                       + (size_t)(i + POS) * (RES * RES)
                       + (size_t)(j + POS) * RES
                       + (size_t)(w + POS);

#pragma unroll
    for (int b = 0; b < BPG; b++) {
        ulonglong2 v; v.x = accL[b]; v.y = accH[b];
        *reinterpret_cast<ulonglong2*>(
            out + (size_t)(b0 + b) * (CH * RES * RES * RES) + obase) = v;
    }
}

extern "C" void kernel_launch(void* const* d_in, const int* in_sizes, int n_in,
                              void* d_out, int out_size)
{
    const float* z  = (const float*)d_in[0];
    const float* U  = (const float*)d_in[1];
    const float* L  = (const float*)d_in[2];
    const float* mu = (const float*)d_in[3];
    float* out = (float*)d_out;

    core_subspace_fused<<<GRID, 256>>>(z, U, L, mu, out);
}

// round 4
// speedup vs baseline: 1.1321x; 1.1321x over previous
#include <cuda_runtime.h>
#include <cstdint>

#define RES   64
#define CH    8
#define NB    64
#define CORE  32
#define POS   16
#define DIMSZ (CORE*CORE*CORE*CH)   // 262144
#define BATCH 32

#define COMPUTE_BLOCKS 512          // 512*256 threads * 2 dims = 262144 dims
#define F4_TOTAL  (BATCH*CH*RES*RES*RES/4)   // 16,777,216 float4
#define F4_PER_TH 8
#define ZERO_BLOCKS (F4_TOTAL / (256 * F4_PER_TH))  // 8192
#define GRID (COMPUTE_BLOCKS + ZERO_BLOCKS)

// Fused kernel:
//  blocks [0, 512):      (L*z)@U + mu, scattered into the core (U read ONCE,
//                        software-pipelined LDGs so latency is hidden)
//  blocks [512, 8704):   zero-fill the periphery with streaming stores
__global__ void __launch_bounds__(256, 2) core_subspace_fused(
    const float* __restrict__ z,   // (32, 64)
    const float* __restrict__ U,   // (64, 262144)
    const float* __restrict__ L,   // (64,)
    const float* __restrict__ mu,  // (262144,)
    float* __restrict__ out)       // (32, 8, 64, 64, 64)
{
    const int tid = threadIdx.x;

    if (blockIdx.x >= COMPUTE_BLOCKS) {
        // ---------------- periphery zero-fill (streaming stores) -----------
        const int zb = blockIdx.x - COMPUTE_BLOCKS;
        const float4 zero4 = make_float4(0.f, 0.f, 0.f, 0.f);
        float4* o4 = reinterpret_cast<float4*>(out);
#pragma unroll
        for (int c = 0; c < F4_PER_TH; c++) {
            const int f = zb * (256 * F4_PER_TH) + c * 256 + tid;
            // f = ((((b*8+ch)*64 + i)*64) + j)*16 + w4
            const unsigned w4 = f & 15;
            const unsigned j  = (f >> 4)  & 63;
            const unsigned i  = (f >> 10) & 63;
            const bool in_core = (i - 16u < 32u) & (j - 16u < 32u) & (w4 - 4u < 8u);
            if (!in_core) __stcs(&o4[f], zero4);   // core written by compute blocks
        }
        return;
    }

    // ---------------- GEMM + scatter ----------------
    // zL packed as duplicated-f32x2 pairs; one LDS.128 broadcast feeds 2 FFMA2.
    __shared__ alignas(16) unsigned long long s_zl[BATCH * NB];  // 16 KB

    for (int idx = tid; idx < BATCH * NB; idx += 256) {
        float v = L[idx & (NB - 1)] * z[idx];
        unsigned int vb = __float_as_uint(v);
        unsigned long long p;
        asm("mov.b64 %0, {%1, %1};" : "=l"(p) : "r"(vb));
        s_zl[idx] = p;
    }
    __syncthreads();

    const int t  = blockIdx.x * 256 + tid;   // 0 .. 131071
    const int d0 = t * 2;                    // even dim index

    const unsigned long long mu2 =
        *reinterpret_cast<const unsigned long long*>(mu + d0);

    unsigned long long acc[BATCH];
#pragma unroll
    for (int b = 0; b < BATCH; b++) acc[b] = mu2;

    const float* Up = U + d0;
    const ulonglong2* zl2 = reinterpret_cast<const ulonglong2*>(s_zl);

    // U row k for this thread, streaming (read-once) load.
#define LDU(k) __ldcs(reinterpret_cast<const unsigned long long*>( \
                      Up + (size_t)(k) * DIMSZ))

    // Software pipeline, depth = 2 kp-pairs (4 U rows in flight).
    unsigned long long u0a = LDU(0), u0b = LDU(1);
    unsigned long long u1a = LDU(2), u1b = LDU(3);

#pragma unroll 4
    for (int kp = 0; kp < NB / 2; kp++) {
        unsigned long long na = 0, nb = 0;
        if (kp < NB / 2 - 2) {               // prefetch kp+2 while computing kp
            na = LDU(2 * kp + 4);
            nb = LDU(2 * kp + 5);
        }
#pragma unroll
        for (int b = 0; b < BATCH; b++) {
            const ulonglong2 zz = zl2[b * (NB / 2) + kp];  // LDS.128 broadcast
            asm("fma.rn.f32x2 %0, %1, %2, %0;" : "+l"(acc[b]) : "l"(u0a), "l"(zz.x));
            asm("fma.rn.f32x2 %0, %1, %2, %0;" : "+l"(acc[b]) : "l"(u0b), "l"(zz.y));
        }
        u0a = u1a; u0b = u1b;
        u1a = na;  u1b = nb;
    }
#undef LDU

    // Scatter the dim pair into the core region.
    // dim = ((c*32 + i)*32 + j)*32 + w   (w = d0 & 31, even -> 8B aligned)
    const int w = d0 & 31;
    const int j = (d0 >> 5) & 31;
    const int i = (d0 >> 10) & 31;
    const int c = d0 >> 15;

    const size_t obase = (size_t)c * (RES * RES * RES)
                       + (size_t)(i + POS) * (RES * RES)
                       + (size_t)(j + POS) * RES
                       + (size_t)(w + POS);

#pragma unroll
    for (int b = 0; b < BATCH; b++) {
        *reinterpret_cast<unsigned long long*>(
            out + (size_t)b * (CH * RES * RES * RES) + obase) = acc[b];
    }
}

extern "C" void kernel_launch(void* const* d_in, const int* in_sizes, int n_in,
                              void* d_out, int out_size)
{
    const float* z  = (const float*)d_in[0];
    const float* U  = (const float*)d_in[1];
    const float* L  = (const float*)d_in[2];
    const float* mu = (const float*)d_in[3];
    float* out = (float*)d_out;

    core_subspace_fused<<<GRID, 256>>>(z, U, L, mu, out);
}

// round 5
// speedup vs baseline: 1.1776x; 1.0402x over previous
#include <cuda_runtime.h>
#include <cstdint>

#define RES   64
#define CH    8
#define NB    64
#define CORE  32
#define POS   16
#define DIMSZ (CORE*CORE*CORE*CH)   // 262144
#define BATCH 32

#define BGROUPS 4                   // 4 batch groups of 8
#define BPG     8                   // batches per thread
#define DPT     8                   // dims per thread
#define COMPUTE_BLOCKS (DIMSZ / (256 * DPT) * BGROUPS)  // 128*4 = 512

#define F4_TOTAL  (BATCH*CH*RES*RES*RES/4)   // 16,777,216 float4
#define F4_PER_TH 8
#define ZERO_BLOCKS (F4_TOTAL / (256 * F4_PER_TH))  // 8192
#define GRID (COMPUTE_BLOCKS + ZERO_BLOCKS)

// Fused kernel:
//  blocks [0, 512):      GEMM+scatter; each thread: 8 dims x 8 batches, so one
//                        broadcast LDS.128 feeds 8 FFMA2 (smem crossbar was the bind)
//  blocks [512, 8704):   zero-fill the periphery with streaming stores
__global__ void __launch_bounds__(256, 2) core_subspace_fused(
    const float* __restrict__ z,   // (32, 64)
    const float* __restrict__ U,   // (64, 262144)
    const float* __restrict__ L,   // (64,)
    const float* __restrict__ mu,  // (262144,)
    float* __restrict__ out)       // (32, 8, 64, 64, 64)
{
    const int tid = threadIdx.x;

    if (blockIdx.x >= COMPUTE_BLOCKS) {
        // ---------------- periphery zero-fill (streaming stores) -----------
        const int zb = blockIdx.x - COMPUTE_BLOCKS;
        const float4 zero4 = make_float4(0.f, 0.f, 0.f, 0.f);
        float4* o4 = reinterpret_cast<float4*>(out);
#pragma unroll
        for (int c = 0; c < F4_PER_TH; c++) {
            const int f = zb * (256 * F4_PER_TH) + c * 256 + tid;
            // f = ((((b*8+ch)*64 + i)*64) + j)*16 + w4
            const unsigned w4 = f & 15;
            const unsigned j  = (f >> 4)  & 63;
            const unsigned i  = (f >> 10) & 63;
            const bool in_core = (i - 16u < 32u) & (j - 16u < 32u) & (w4 - 4u < 8u);
            if (!in_core) __stcs(&o4[f], zero4);   // core written by compute blocks
        }
        return;
    }

    // ---------------- GEMM + scatter ----------------
    // zL packed as duplicated-f32x2 pairs; one LDS.128 broadcast per (b, kp).
    __shared__ alignas(16) unsigned long long s_zl[BATCH * NB];  // 16 KB

    for (int idx = tid; idx < BATCH * NB; idx += 256) {
        float v = L[idx & (NB - 1)] * z[idx];
        unsigned int vb = __float_as_uint(v);
        unsigned long long p;
        asm("mov.b64 %0, {%1, %1};" : "=l"(p) : "r"(vb));
        s_zl[idx] = p;
    }
    __syncthreads();

    // Group-minor: 4 blocks with the same dim-chunk but different batch groups
    // run concurrently -> U re-reads hit L2 (whole U fits in 126MB L2).
    const int bg       = blockIdx.x & (BGROUPS - 1);
    const int dimchunk = blockIdx.x >> 2;            // 0..127
    const int b0       = bg * BPG;

    const int d0 = (dimchunk * 256 + tid) * DPT;     // dim index, multiple of 8

    const ulonglong2 mu_a = *reinterpret_cast<const ulonglong2*>(mu + d0);
    const ulonglong2 mu_b = *reinterpret_cast<const ulonglong2*>(mu + d0 + 4);

    unsigned long long acc[BPG][4];
#pragma unroll
    for (int b = 0; b < BPG; b++) {
        acc[b][0] = mu_a.x; acc[b][1] = mu_a.y;
        acc[b][2] = mu_b.x; acc[b][3] = mu_b.y;
    }

    const float* Up = U + d0;
    const ulonglong2* zl2 = reinterpret_cast<const ulonglong2*>(s_zl);

#define LDU(k, off) (*reinterpret_cast<const ulonglong2*>( \
                     Up + (size_t)(k) * DIMSZ + (off)))

    // Software pipeline depth 1: next kp-pair's 4 LDG.128 in flight during FMAs.
    ulonglong2 ua0 = LDU(0, 0), ua1 = LDU(0, 4);   // k = 2*kp
    ulonglong2 ub0 = LDU(1, 0), ub1 = LDU(1, 4);   // k = 2*kp+1

#pragma unroll 2
    for (int kp = 0; kp < NB / 2; kp++) {
        ulonglong2 na0, na1, nb0, nb1;
        if (kp < NB / 2 - 1) {
            na0 = LDU(2 * kp + 2, 0); na1 = LDU(2 * kp + 2, 4);
            nb0 = LDU(2 * kp + 3, 0); nb1 = LDU(2 * kp + 3, 4);
        }
#pragma unroll
        for (int b = 0; b < BPG; b++) {
            const ulonglong2 zz = zl2[(b0 + b) * (NB / 2) + kp];  // LDS.128 bcast
            asm("fma.rn.f32x2 %0, %1, %2, %0;" : "+l"(acc[b][0]) : "l"(ua0.x), "l"(zz.x));
            asm("fma.rn.f32x2 %0, %1, %2, %0;" : "+l"(acc[b][1]) : "l"(ua0.y), "l"(zz.x));
            asm("fma.rn.f32x2 %0, %1, %2, %0;" : "+l"(acc[b][2]) : "l"(ua1.x), "l"(zz.x));
            asm("fma.rn.f32x2 %0, %1, %2, %0;" : "+l"(acc[b][3]) : "l"(ua1.y), "l"(zz.x));
            asm("fma.rn.f32x2 %0, %1, %2, %0;" : "+l"(acc[b][0]) : "l"(ub0.x), "l"(zz.y));
            asm("fma.rn.f32x2 %0, %1, %2, %0;" : "+l"(acc[b][1]) : "l"(ub0.y), "l"(zz.y));
            asm("fma.rn.f32x2 %0, %1, %2, %0;" : "+l"(acc[b][2]) : "l"(ub1.x), "l"(zz.y));
            asm("fma.rn.f32x2 %0, %1, %2, %0;" : "+l"(acc[b][3]) : "l"(ub1.y), "l"(zz.y));
        }
        ua0 = na0; ua1 = na1; ub0 = nb0; ub1 = nb1;
    }
#undef LDU

    // Scatter the 8-dim chunk into the core region.
    // dim = ((c*32 + i)*32 + j)*32 + w ; w = d0&31 in {0,8,16,24} -> 16B aligned
    const int w = d0 & 31;
    const int j = (d0 >> 5) & 31;
    const int i = (d0 >> 10) & 31;
    const int c = d0 >> 15;

    const size_t obase = (size_t)c * (RES * RES * RES)
                       + (size_t)(i + POS) * (RES * RES)
                       + (size_t)(j + POS) * RES
                       + (size_t)(w + POS);

#pragma unroll
    for (int b = 0; b < BPG; b++) {
        float* o = out + (size_t)(b0 + b) * (CH * RES * RES * RES) + obase;
        ulonglong2 v0; v0.x = acc[b][0]; v0.y = acc[b][1];
        ulonglong2 v1; v1.x = acc[b][2]; v1.y = acc[b][3];
        *reinterpret_cast<ulonglong2*>(o)     = v0;
        *reinterpret_cast<ulonglong2*>(o + 4) = v1;
    }
}

extern "C" void kernel_launch(void* const* d_in, const int* in_sizes, int n_in,
                              void* d_out, int out_size)
{
    const float* z  = (const float*)d_in[0];
    const float* U  = (const float*)d_in[1];
    const float* L  = (const float*)d_in[2];
    const float* mu = (const float*)d_in[3];
    float* out = (float*)d_out;

    core_subspace_fused<<<GRID, 256>>>(z, U, L, mu, out);
}